// round 14
// baseline (speedup 1.0000x reference)
#include <cuda_runtime.h>
#include <math.h>

#define D 128
#define MAXN 100000
#define MAXR 64
#define MAXE 600000
#define SCAN_B 1024
#define MAXBLK 128
#define IDXBITS 17
#define IDXMASK ((1u << IDXBITS) - 1u)

// ---- device-global scratch (alloc-free rule) ----
__device__ float    g_V[MAXR * 2 * D];
__device__ float    g_scr_u[(size_t)MAXN * D];
__device__ float    g_scr_i[(size_t)MAXN * D];
__device__ int      g_deg_u[MAXN], g_deg_i[MAXN];
__device__ int      g_off_u[MAXN + 1], g_off_i[MAXN + 1];
__device__ int      g_cur_u[MAXN], g_cur_i[MAXN];
__device__ int      g_part_u[MAXBLK], g_part_i[MAXBLK];
__device__ unsigned g_adj_u[MAXE];     // packed: idx | (rel << IDXBITS)
__device__ unsigned g_adj_i[MAXE];

// Streaming row load: bypass L1 (no allocate), normal L2 policy.
// Keeps the V table + adj stream resident in L1.
__device__ __forceinline__ float4 ldg_na(const float4* p) {
    float4 v;
    asm("ld.global.nc.L1::no_allocate.v4.f32 {%0,%1,%2,%3}, [%4];"
        : "=f"(v.x), "=f"(v.y), "=f"(v.z), "=f"(v.w) : "l"(p));
    return v;
}

// Blocks < R compute V[r]; all blocks zero degree arrays.
__global__ void compute_V_init(const float* __restrict__ W,
                               const float* __restrict__ rel,
                               int R, int Nu, int Ne) {
    if (blockIdx.x < R) {
        __shared__ float srel[D];
        int r = blockIdx.x, j = threadIdx.x;
        if (j < D) srel[j] = rel[r * D + j];
        __syncthreads();
        float acc = 0.f;
#pragma unroll 8
        for (int k = 0; k < D; k++) acc = fmaf(W[j * D + k], srel[k], acc);
        g_V[r * 2 * D + j] = acc;
    }
    int idx = blockIdx.x * blockDim.x + threadIdx.x;
    int T = gridDim.x * blockDim.x;
    for (int k = idx; k < Nu; k += T) g_deg_u[k] = 0;
    for (int k = idx; k < Ne; k += T) g_deg_i[k] = 0;
}

__global__ void hist_kernel(const int* __restrict__ head,
                            const int* __restrict__ tail, int E) {
    int i = blockIdx.x * blockDim.x + threadIdx.x;
    if (i < E) {
        atomicAdd(g_deg_u + head[i], 1);
        atomicAdd(g_deg_i + tail[i], 1);
    }
}

__global__ void scan_partial(int Nu, int Ne, int nblk_u) {
    int b = blockIdx.x;
    const int* deg; int* part; int N, lb;
    if (b < nblk_u) { deg = g_deg_u; part = g_part_u; N = Nu; lb = b; }
    else            { deg = g_deg_i; part = g_part_i; N = Ne; lb = b - nblk_u; }
    int tid = threadIdx.x, lane = tid & 31, wid = tid >> 5;
    int i = lb * SCAN_B + tid;
    int v = (i < N) ? deg[i] : 0;
    __shared__ int wsum[32];
#pragma unroll
    for (int o = 16; o; o >>= 1) v += __shfl_xor_sync(0xffffffffu, v, o);
    if (lane == 0) wsum[wid] = v;
    __syncthreads();
    if (wid == 0) {
        int s = wsum[lane];
#pragma unroll
        for (int o = 16; o; o >>= 1) s += __shfl_xor_sync(0xffffffffu, s, o);
        if (lane == 0) part[lb] = s;
    }
}

__global__ void scan_final(int Nu, int Ne, int nblk_u, int nblk_i) {
    int b = blockIdx.x;
    const int* deg; const int* part; int* off; int* cur; int N, lb, nblk;
    if (b < nblk_u) { deg = g_deg_u; part = g_part_u; off = g_off_u; cur = g_cur_u;
                      N = Nu; lb = b; nblk = nblk_u; }
    else            { deg = g_deg_i; part = g_part_i; off = g_off_i; cur = g_cur_i;
                      N = Ne; lb = b - nblk_u; nblk = nblk_i; }
    int tid = threadIdx.x, lane = tid & 31, wid = tid >> 5;
    __shared__ int s_carry, s_total;
    __shared__ int wsum[32];
    if (wid == 0) {
        int c = 0, t = 0;
        for (int j = lane; j < nblk; j += 32) {
            int p = part[j];
            t += p;
            if (j < lb) c += p;
        }
#pragma unroll
        for (int o = 16; o; o >>= 1) {
            c += __shfl_xor_sync(0xffffffffu, c, o);
            t += __shfl_xor_sync(0xffffffffu, t, o);
        }
        if (lane == 0) { s_carry = c; s_total = t; }
    }
    __syncthreads();
    int i = lb * SCAN_B + tid;
    int v = (i < N) ? deg[i] : 0;
    int x = v;
#pragma unroll
    for (int o = 1; o < 32; o <<= 1) {
        int y = __shfl_up_sync(0xffffffffu, x, o);
        if (lane >= o) x += y;
    }
    if (lane == 31) wsum[wid] = x;
    __syncthreads();
    if (wid == 0) {
        int s = wsum[lane];
#pragma unroll
        for (int o = 1; o < 32; o <<= 1) {
            int y = __shfl_up_sync(0xffffffffu, s, o);
            if (lane >= o) s += y;
        }
        wsum[lane] = s;
    }
    __syncthreads();
    int incl = x + (wid ? wsum[wid - 1] : 0);
    int excl = incl - v + s_carry;
    if (i < N) { off[i] = excl; cur[i] = excl; }
    if (lb == 0 && tid == 0) off[N] = s_total;
}

__global__ void scatter_kernel(const int* __restrict__ head,
                               const int* __restrict__ tail,
                               const int* __restrict__ etype, int E) {
    int i = blockIdx.x * blockDim.x + threadIdx.x;
    if (i < E) {
        int h = head[i], t = tail[i];
        unsigned rbits = ((unsigned)etype[i]) << IDXBITS;
        g_adj_u[atomicAdd(g_cur_u + h, 1)] = (unsigned)t | rbits;
        g_adj_i[atomicAdd(g_cur_i + t, 1)] = (unsigned)h | rbits;
    }
}

// Fused both-sides hop kernel (round-11 winner). One warp per node, row in
// registers, depth-2 pipeline. Gather + self rows bypass L1 (no_allocate) so
// the V table stays L1-resident.
__global__ __launch_bounds__(256)
void agg2_kernel(const float* __restrict__ usr, const float* __restrict__ ent,
                 float* __restrict__ usr_o, float* __restrict__ ent_o,
                 int Nu, int Ne, int gu) {
    int b = blockIdx.x;
    const float* self; const float* other; float* dst;
    const int* off; const unsigned* adj; int N, voff_own, voff_oth, nb;
    if (b < gu) { self = usr; other = ent; dst = usr_o; off = g_off_u;
                  adj = g_adj_u; N = Nu; voff_own = 0; voff_oth = D; nb = b; }
    else        { self = ent; other = usr; dst = ent_o; off = g_off_i;
                  adj = g_adj_i; N = Ne; voff_own = D; voff_oth = 0; nb = b - gu; }
    int wid = threadIdx.x >> 5, lane = threadIdx.x & 31;
    int node = nb * 8 + wid;
    if (node >= N) return;

    int beg = off[node];
    int n = off[node + 1] - beg;
    float4 own = ldg_na((const float4*)(self + (size_t)node * D) + lane);
    float4 num = make_float4(0.f, 0.f, 0.f, 0.f);
    float den = 0.f;

    // depth-2 pipeline over edges (adj + oth row only)
    unsigned ad0 = 0, ad1 = 0; float4 o0, o1;
    if (n > 0) {
        ad0 = __ldg(adj + beg);
        o0 = ldg_na((const float4*)(other + (size_t)(ad0 & IDXMASK) * D) + lane);
    }
    if (n > 1) {
        ad1 = __ldg(adj + beg + 1);
        o1 = ldg_na((const float4*)(other + (size_t)(ad1 & IDXMASK) * D) + lane);
    }
    for (int e = 0; e < n; e++) {
        unsigned ad = ad0; float4 oth = o0;
        ad0 = ad1; o0 = o1;
        if (e + 2 < n) {
            ad1 = __ldg(adj + beg + e + 2);
            o1 = ldg_na((const float4*)(other + (size_t)(ad1 & IDXMASK) * D) + lane);
        }
        int r = ad >> IDXBITS;
        float4 vo = __ldg((const float4*)(g_V + r * 2 * D + voff_own) + lane);
        float4 vw = __ldg((const float4*)(g_V + r * 2 * D + voff_oth) + lane);
        float p = own.x * vo.x + own.y * vo.y + own.z * vo.z + own.w * vo.w
                + oth.x * vw.x + oth.y * vw.y + oth.z * vw.z + oth.w * vw.w;
#pragma unroll
        for (int o = 16; o; o >>= 1) p += __shfl_xor_sync(0xffffffffu, p, o);
        float s = p > 0.f ? p : 0.2f * p;            // LeakyReLU(0.2)
        float ee = __expf(s);
        num.x = fmaf(oth.x, ee, num.x);
        num.y = fmaf(oth.y, ee, num.y);
        num.z = fmaf(oth.z, ee, num.z);
        num.w = fmaf(oth.w, ee, num.w);
        den += ee;
    }
    float inv = den > 0.f ? 1.f / den : 0.f;
    float4 a;
    a.x = fmaf(num.x, inv, own.x);
    a.y = fmaf(num.y, inv, own.y);
    a.z = fmaf(num.z, inv, own.z);
    a.w = fmaf(num.w, inv, own.w);
    float ss = a.x * a.x + a.y * a.y + a.z * a.z + a.w * a.w;
#pragma unroll
    for (int o = 16; o; o >>= 1) ss += __shfl_xor_sync(0xffffffffu, ss, o);
    float sc = 1.f / fmaxf(sqrtf(ss), 1e-8f);
    float4 out;
    out.x = fmaf(a.x, sc, own.x);
    out.y = fmaf(a.y, sc, own.y);
    out.z = fmaf(a.z, sc, own.z);
    out.w = fmaf(a.w, sc, own.w);
    __stcs((float4*)(dst + (size_t)node * D) + lane, out);
}

extern "C" void kernel_launch(void* const* d_in, const int* in_sizes, int n_in,
                              void* d_out, int out_size) {
    const float* usr_in = (const float*)d_in[0];
    const float* rel    = (const float*)d_in[1];
    const float* ent_in = (const float*)d_in[2];
    const float* W      = (const float*)d_in[3];
    const int*   eidx   = (const int*)d_in[4];
    const int*   etype  = (const int*)d_in[5];

    int Nu = in_sizes[0] / D;
    int R  = in_sizes[1] / D;
    int Ne = in_sizes[2] / D;
    int E  = in_sizes[5];

    float* usr_out = (float*)d_out;
    float* ent_out = usr_out + (size_t)Nu * D;

    void *p_su, *p_si;
    cudaGetSymbolAddress(&p_su, g_scr_u);
    cudaGetSymbolAddress(&p_si, g_scr_i);
    float* scr_u = (float*)p_su;
    float* scr_i = (float*)p_si;

    const int* head = eidx;
    const int* tail = eidx + E;

    int nblk_u = (Nu + SCAN_B - 1) / SCAN_B;
    int nblk_i = (Ne + SCAN_B - 1) / SCAN_B;
    int gu = (Nu + 7) / 8, gi = (Ne + 7) / 8;

    compute_V_init<<<1024, 2 * D>>>(W, rel, R, Nu, Ne);
    hist_kernel<<<(E + 255) / 256, 256>>>(head, tail, E);
    scan_partial<<<nblk_u + nblk_i, SCAN_B>>>(Nu, Ne, nblk_u);
    scan_final<<<nblk_u + nblk_i, SCAN_B>>>(Nu, Ne, nblk_u, nblk_i);
    scatter_kernel<<<(E + 255) / 256, 256>>>(head, tail, etype, E);

    agg2_kernel<<<gu + gi, 256>>>(usr_in, ent_in, scr_u, scr_i, Nu, Ne, gu);
    agg2_kernel<<<gu + gi, 256>>>(scr_u, scr_i, usr_out, ent_out, Nu, Ne, gu);
}

// round 16
// speedup vs baseline: 1.0687x; 1.0687x over previous
#include <cuda_runtime.h>
#include <math.h>

#define D 128
#define MAXN 100000
#define MAXR 64
#define MAXE 600000
#define SCAN_B 1024
#define MAXBLK 128
#define IDXBITS 17
#define IDXMASK ((1u << IDXBITS) - 1u)

// ---- device-global scratch (alloc-free rule) ----
__device__ float    g_V[MAXR * 2 * D];
__device__ float    g_scr_u[(size_t)MAXN * D];
__device__ float    g_scr_i[(size_t)MAXN * D];
__device__ int      g_deg_u[MAXN], g_deg_i[MAXN];
__device__ int      g_off_u[MAXN + 1], g_off_i[MAXN + 1];
__device__ int      g_cur_u[MAXN], g_cur_i[MAXN];
__device__ int      g_part_u[MAXBLK], g_part_i[MAXBLK];
__device__ unsigned g_adj_u[MAXE];     // packed: idx | (rel << IDXBITS)
__device__ unsigned g_adj_i[MAXE];

// Blocks < R compute V[r]; all blocks zero degree arrays.
__global__ void compute_V_init(const float* __restrict__ W,
                               const float* __restrict__ rel,
                               int R, int Nu, int Ne) {
    if (blockIdx.x < R) {
        __shared__ float srel[D];
        int r = blockIdx.x, j = threadIdx.x;
        if (j < D) srel[j] = rel[r * D + j];
        __syncthreads();
        float acc = 0.f;
#pragma unroll 8
        for (int k = 0; k < D; k++) acc = fmaf(W[j * D + k], srel[k], acc);
        g_V[r * 2 * D + j] = acc;
    }
    int idx = blockIdx.x * blockDim.x + threadIdx.x;
    int T = gridDim.x * blockDim.x;
    for (int k = idx; k < Nu; k += T) g_deg_u[k] = 0;
    for (int k = idx; k < Ne; k += T) g_deg_i[k] = 0;
}

__global__ void hist_kernel(const int* __restrict__ head,
                            const int* __restrict__ tail, int E) {
    int i = blockIdx.x * blockDim.x + threadIdx.x;
    if (i < E) {
        atomicAdd(g_deg_u + head[i], 1);
        atomicAdd(g_deg_i + tail[i], 1);
    }
}

__global__ void scan_partial(int Nu, int Ne, int nblk_u) {
    int b = blockIdx.x;
    const int* deg; int* part; int N, lb;
    if (b < nblk_u) { deg = g_deg_u; part = g_part_u; N = Nu; lb = b; }
    else            { deg = g_deg_i; part = g_part_i; N = Ne; lb = b - nblk_u; }
    int tid = threadIdx.x, lane = tid & 31, wid = tid >> 5;
    int i = lb * SCAN_B + tid;
    int v = (i < N) ? deg[i] : 0;
    __shared__ int wsum[32];
#pragma unroll
    for (int o = 16; o; o >>= 1) v += __shfl_xor_sync(0xffffffffu, v, o);
    if (lane == 0) wsum[wid] = v;
    __syncthreads();
    if (wid == 0) {
        int s = wsum[lane];
#pragma unroll
        for (int o = 16; o; o >>= 1) s += __shfl_xor_sync(0xffffffffu, s, o);
        if (lane == 0) part[lb] = s;
    }
}

__global__ void scan_final(int Nu, int Ne, int nblk_u, int nblk_i) {
    int b = blockIdx.x;
    const int* deg; const int* part; int* off; int* cur; int N, lb, nblk;
    if (b < nblk_u) { deg = g_deg_u; part = g_part_u; off = g_off_u; cur = g_cur_u;
                      N = Nu; lb = b; nblk = nblk_u; }
    else            { deg = g_deg_i; part = g_part_i; off = g_off_i; cur = g_cur_i;
                      N = Ne; lb = b - nblk_u; nblk = nblk_i; }
    int tid = threadIdx.x, lane = tid & 31, wid = tid >> 5;
    __shared__ int s_carry, s_total;
    __shared__ int wsum[32];
    if (wid == 0) {
        int c = 0, t = 0;
        for (int j = lane; j < nblk; j += 32) {
            int p = part[j];
            t += p;
            if (j < lb) c += p;
        }
#pragma unroll
        for (int o = 16; o; o >>= 1) {
            c += __shfl_xor_sync(0xffffffffu, c, o);
            t += __shfl_xor_sync(0xffffffffu, t, o);
        }
        if (lane == 0) { s_carry = c; s_total = t; }
    }
    __syncthreads();
    int i = lb * SCAN_B + tid;
    int v = (i < N) ? deg[i] : 0;
    int x = v;
#pragma unroll
    for (int o = 1; o < 32; o <<= 1) {
        int y = __shfl_up_sync(0xffffffffu, x, o);
        if (lane >= o) x += y;
    }
    if (lane == 31) wsum[wid] = x;
    __syncthreads();
    if (wid == 0) {
        int s = wsum[lane];
#pragma unroll
        for (int o = 1; o < 32; o <<= 1) {
            int y = __shfl_up_sync(0xffffffffu, s, o);
            if (lane >= o) s += y;
        }
        wsum[lane] = s;
    }
    __syncthreads();
    int incl = x + (wid ? wsum[wid - 1] : 0);
    int excl = incl - v + s_carry;
    if (i < N) { off[i] = excl; cur[i] = excl; }
    if (lb == 0 && tid == 0) off[N] = s_total;
}

__global__ void scatter_kernel(const int* __restrict__ head,
                               const int* __restrict__ tail,
                               const int* __restrict__ etype, int E) {
    int i = blockIdx.x * blockDim.x + threadIdx.x;
    if (i < E) {
        int h = head[i], t = tail[i];
        unsigned rbits = ((unsigned)etype[i]) << IDXBITS;
        g_adj_u[atomicAdd(g_cur_u + h, 1)] = (unsigned)t | rbits;
        g_adj_i[atomicAdd(g_cur_i + t, 1)] = (unsigned)h | rbits;
    }
}

// Fused both-sides hop kernel (round-11 winner), edges processed in PAIRS so
// the two 5-step shuffle-reduction chains overlap.
__global__ __launch_bounds__(256)
void agg2_kernel(const float* __restrict__ usr, const float* __restrict__ ent,
                 float* __restrict__ usr_o, float* __restrict__ ent_o,
                 int Nu, int Ne, int gu) {
    int b = blockIdx.x;
    const float* self; const float* other; float* dst;
    const int* off; const unsigned* adj; int N, voff_own, voff_oth, nb;
    if (b < gu) { self = usr; other = ent; dst = usr_o; off = g_off_u;
                  adj = g_adj_u; N = Nu; voff_own = 0; voff_oth = D; nb = b; }
    else        { self = ent; other = usr; dst = ent_o; off = g_off_i;
                  adj = g_adj_i; N = Ne; voff_own = D; voff_oth = 0; nb = b - gu; }
    int wid = threadIdx.x >> 5, lane = threadIdx.x & 31;
    int node = nb * 8 + wid;
    if (node >= N) return;

    int beg = off[node];
    int n = off[node + 1] - beg;
    float4 own = __ldcs((const float4*)(self + (size_t)node * D) + lane);
    float4 num = make_float4(0.f, 0.f, 0.f, 0.f);
    float den = 0.f;

    unsigned ad0 = 0, ad1 = 0; float4 o0, o1;
    if (n > 0) {
        ad0 = __ldg(adj + beg);
        o0 = __ldg((const float4*)(other + (size_t)(ad0 & IDXMASK) * D) + lane);
    }
    if (n > 1) {
        ad1 = __ldg(adj + beg + 1);
        o1 = __ldg((const float4*)(other + (size_t)(ad1 & IDXMASK) * D) + lane);
    }

    int e = 0;
    for (; e + 1 < n; e += 2) {
        unsigned ada = ad0, adb = ad1;
        float4 oa = o0, ob = o1;
        if (e + 2 < n) {
            ad0 = __ldg(adj + beg + e + 2);
            o0 = __ldg((const float4*)(other + (size_t)(ad0 & IDXMASK) * D) + lane);
        }
        if (e + 3 < n) {
            ad1 = __ldg(adj + beg + e + 3);
            o1 = __ldg((const float4*)(other + (size_t)(ad1 & IDXMASK) * D) + lane);
        }
        int ra = ada >> IDXBITS, rb = adb >> IDXBITS;
        float4 voa = __ldg((const float4*)(g_V + ra * 2 * D + voff_own) + lane);
        float4 vwa = __ldg((const float4*)(g_V + ra * 2 * D + voff_oth) + lane);
        float4 vob = __ldg((const float4*)(g_V + rb * 2 * D + voff_own) + lane);
        float4 vwb = __ldg((const float4*)(g_V + rb * 2 * D + voff_oth) + lane);
        float pa = own.x * voa.x + own.y * voa.y + own.z * voa.z + own.w * voa.w
                 + oa.x * vwa.x + oa.y * vwa.y + oa.z * vwa.z + oa.w * vwa.w;
        float pb = own.x * vob.x + own.y * vob.y + own.z * vob.z + own.w * vob.w
                 + ob.x * vwb.x + ob.y * vwb.y + ob.z * vwb.z + ob.w * vwb.w;
#pragma unroll
        for (int o = 16; o; o >>= 1) {                // two independent chains
            pa += __shfl_xor_sync(0xffffffffu, pa, o);
            pb += __shfl_xor_sync(0xffffffffu, pb, o);
        }
        float sa = pa > 0.f ? pa : 0.2f * pa;
        float sb = pb > 0.f ? pb : 0.2f * pb;
        float ea = __expf(sa);
        float eb = __expf(sb);
        num.x = fmaf(oa.x, ea, fmaf(ob.x, eb, num.x));
        num.y = fmaf(oa.y, ea, fmaf(ob.y, eb, num.y));
        num.z = fmaf(oa.z, ea, fmaf(ob.z, eb, num.z));
        num.w = fmaf(oa.w, ea, fmaf(ob.w, eb, num.w));
        den += ea + eb;
    }
    if (e < n) {                                      // odd remainder
        int r = ad0 >> IDXBITS;
        float4 vo = __ldg((const float4*)(g_V + r * 2 * D + voff_own) + lane);
        float4 vw = __ldg((const float4*)(g_V + r * 2 * D + voff_oth) + lane);
        float p = own.x * vo.x + own.y * vo.y + own.z * vo.z + own.w * vo.w
                + o0.x * vw.x + o0.y * vw.y + o0.z * vw.z + o0.w * vw.w;
#pragma unroll
        for (int o = 16; o; o >>= 1) p += __shfl_xor_sync(0xffffffffu, p, o);
        float s = p > 0.f ? p : 0.2f * p;
        float ee = __expf(s);
        num.x = fmaf(o0.x, ee, num.x);
        num.y = fmaf(o0.y, ee, num.y);
        num.z = fmaf(o0.z, ee, num.z);
        num.w = fmaf(o0.w, ee, num.w);
        den += ee;
    }

    float inv = den > 0.f ? 1.f / den : 0.f;
    float4 a;
    a.x = fmaf(num.x, inv, own.x);
    a.y = fmaf(num.y, inv, own.y);
    a.z = fmaf(num.z, inv, own.z);
    a.w = fmaf(num.w, inv, own.w);
    float ss = a.x * a.x + a.y * a.y + a.z * a.z + a.w * a.w;
#pragma unroll
    for (int o = 16; o; o >>= 1) ss += __shfl_xor_sync(0xffffffffu, ss, o);
    float sc = 1.f / fmaxf(sqrtf(ss), 1e-8f);
    float4 out;
    out.x = fmaf(a.x, sc, own.x);
    out.y = fmaf(a.y, sc, own.y);
    out.z = fmaf(a.z, sc, own.z);
    out.w = fmaf(a.w, sc, own.w);
    __stcs((float4*)(dst + (size_t)node * D) + lane, out);
}

extern "C" void kernel_launch(void* const* d_in, const int* in_sizes, int n_in,
                              void* d_out, int out_size) {
    const float* usr_in = (const float*)d_in[0];
    const float* rel    = (const float*)d_in[1];
    const float* ent_in = (const float*)d_in[2];
    const float* W      = (const float*)d_in[3];
    const int*   eidx   = (const int*)d_in[4];
    const int*   etype  = (const int*)d_in[5];

    int Nu = in_sizes[0] / D;
    int R  = in_sizes[1] / D;
    int Ne = in_sizes[2] / D;
    int E  = in_sizes[5];

    float* usr_out = (float*)d_out;
    float* ent_out = usr_out + (size_t)Nu * D;

    void *p_su, *p_si;
    cudaGetSymbolAddress(&p_su, g_scr_u);
    cudaGetSymbolAddress(&p_si, g_scr_i);
    float* scr_u = (float*)p_su;
    float* scr_i = (float*)p_si;

    const int* head = eidx;
    const int* tail = eidx + E;

    int nblk_u = (Nu + SCAN_B - 1) / SCAN_B;
    int nblk_i = (Ne + SCAN_B - 1) / SCAN_B;
    int gu = (Nu + 7) / 8, gi = (Ne + 7) / 8;

    compute_V_init<<<1024, 2 * D>>>(W, rel, R, Nu, Ne);
    hist_kernel<<<(E + 255) / 256, 256>>>(head, tail, E);
    scan_partial<<<nblk_u + nblk_i, SCAN_B>>>(Nu, Ne, nblk_u);
    scan_final<<<nblk_u + nblk_i, SCAN_B>>>(Nu, Ne, nblk_u, nblk_i);
    scatter_kernel<<<(E + 255) / 256, 256>>>(head, tail, etype, E);

    agg2_kernel<<<gu + gi, 256>>>(usr_in, ent_in, scr_u, scr_i, Nu, Ne, gu);
    agg2_kernel<<<gu + gi, 256>>>(scr_u, scr_i, usr_out, ent_out, Nu, Ne, gu);
}